// round 1
// baseline (speedup 1.0000x reference)
#include <cuda_runtime.h>
#include <math.h>

// out[b,l,c,e] = A[e] + ds * Bv[e]
//   ds = valid ? mat2[row, c] : 0
//   A[e]  = esl[m][e] + (etl[m][e]*(TU - t) + etu[m][e]*t) / TU
//   Bv[e] = (esu[m][e] - esl[m][e]) / SU
// SU=500, TU=3600 (SL=TL=0)

__global__ void __launch_bounds__(256) embed_kernel(
    const int*   __restrict__ traj_loc,   // (B*L)
    const float* __restrict__ mat2,       // (LOC, LOC)
    const float* __restrict__ vec,        // (B*L)
    const int*   __restrict__ traj_len,   // (B)
    const float* __restrict__ emb_sl,     // (2, E)
    const float* __restrict__ emb_su,
    const float* __restrict__ emb_tl,
    const float* __restrict__ emb_tu,
    float*       __restrict__ out,        // (B, L, LOC, E)
    int L, int LOC, int E)
{
    const int bl = blockIdx.x;
    const int b  = bl / L;
    const int l  = bl - b * L;

    const bool valid = (l < traj_len[b]);
    const int  m     = valid ? 1 : 0;
    const float t    = vec[bl];

    int row = traj_loc[bl] - 1;
    row = row < 0 ? 0 : (row > LOC - 1 ? LOC - 1 : row);

    const int EQ = E >> 2;                 // float4 groups per c (E=16 -> 4)
    const int q  = threadIdx.x & (EQ - 1); // this thread's e-group (stride 256 % EQ == 0)

    const float4 esl = reinterpret_cast<const float4*>(emb_sl + m * E)[q];
    const float4 esu = reinterpret_cast<const float4*>(emb_su + m * E)[q];
    const float4 etl = reinterpret_cast<const float4*>(emb_tl + m * E)[q];
    const float4 etu = reinterpret_cast<const float4*>(emb_tu + m * E)[q];

    const float invS = 1.0f / 500.0f;   // 1/(SU-SL)
    const float invT = 1.0f / 3600.0f;  // 1/(TU-TL)
    const float TUv  = 3600.0f;

    float4 A, Bv;
    A.x = fmaf(fmaf(etl.x, TUv - t, etu.x * t), invT, esl.x);
    A.y = fmaf(fmaf(etl.y, TUv - t, etu.y * t), invT, esl.y);
    A.z = fmaf(fmaf(etl.z, TUv - t, etu.z * t), invT, esl.z);
    A.w = fmaf(fmaf(etl.w, TUv - t, etu.w * t), invT, esl.w);
    Bv.x = (esu.x - esl.x) * invS;
    Bv.y = (esu.y - esl.y) * invS;
    Bv.z = (esu.z - esl.z) * invS;
    Bv.w = (esu.w - esl.w) * invS;

    const float* __restrict__ mrow = mat2 + (size_t)row * LOC;
    float4* __restrict__ o = reinterpret_cast<float4*>(out + (size_t)bl * LOC * E);

    const int n4 = LOC * EQ;  // float4 elements per (b,l) tile
    if (valid) {
        #pragma unroll 4
        for (int i = threadIdx.x; i < n4; i += 256) {
            const int c = i / EQ;
            const float ds = __ldg(mrow + c);
            float4 v;
            v.x = fmaf(ds, Bv.x, A.x);
            v.y = fmaf(ds, Bv.y, A.y);
            v.z = fmaf(ds, Bv.z, A.z);
            v.w = fmaf(ds, Bv.w, A.w);
            o[i] = v;
        }
    } else {
        #pragma unroll 4
        for (int i = threadIdx.x; i < n4; i += 256) {
            o[i] = A;  // ds == 0
        }
    }
}

extern "C" void kernel_launch(void* const* d_in, const int* in_sizes, int n_in,
                              void* d_out, int out_size)
{
    const int*   traj_loc = (const int*)  d_in[0];
    const float* mat2     = (const float*)d_in[1];
    const float* vec      = (const float*)d_in[2];
    const int*   traj_len = (const int*)  d_in[3];
    const float* emb_sl   = (const float*)d_in[4];
    const float* emb_su   = (const float*)d_in[5];
    const float* emb_tl   = (const float*)d_in[6];
    const float* emb_tu   = (const float*)d_in[7];

    const int BL  = in_sizes[0];                       // B*L
    const int B   = in_sizes[3];
    const int L   = BL / B;
    const int LOC = (int)(sqrt((double)in_sizes[1]) + 0.5);
    const int E   = in_sizes[4] / 2;

    embed_kernel<<<BL, 256>>>(traj_loc, mat2, vec, traj_len,
                              emb_sl, emb_su, emb_tl, emb_tu,
                              (float*)d_out, L, LOC, E);
}